// round 16
// baseline (speedup 1.0000x reference)
#include <cuda_runtime.h>
#include <cstdint>

#define S_LEN 2048
#define DIM   64
#define NT    32                      // 64-key tiles
#define SCL   0.18033688011112042f    // 0.125 * log2(e)
#define L2E   1.4426950408889634f

__device__ float g_rowsum[64 * S_LEN];

// ---- kernel A smem (floats) ----
#define KF(b)   ((b) * 5120)
#define MSA(b)  (10240 + (b) * 64)
#define SMA_FLOATS 10368
// ---- kernel B smem (floats) ----
#define VF(b)   ((b) * 5120)          // V frags, double buffer (40 KB)
#define PS_OFF  10240                 // staging: 8 warps * 16 rows * 20 = 2560
#define SMB_FLOATS 12800              // 51200 bytes -> 3 CTAs/SM

__device__ __forceinline__ float tff(float x) {      // round-to-nearest tf32
    uint32_t u;
    asm("cvt.rna.tf32.f32 %0, %1;" : "=r"(u) : "f"(x));
    return __uint_as_float(u);
}

__device__ __forceinline__ float exp2_poly(float t) {
    float z = t + 12582912.0f;
    int   j = __float_as_int(z) - 0x4B400000;
    float f = t - (z - 12582912.0f);
    float p =            1.33335581e-3f;
    p = fmaf(p, f, 9.61812910e-3f);
    p = fmaf(p, f, 5.55041087e-2f);
    p = fmaf(p, f, 2.40226507e-1f);
    p = fmaf(p, f, 6.93147180e-1f);
    p = fmaf(p, f, 1.0f);
    return __int_as_float(__float_as_int(p) + (j << 23));
}

#define MMA_TF32(d, a, b0, b1)                                               \
    asm volatile("mma.sync.aligned.m16n8k8.row.col.f32.tf32.tf32.f32 "       \
        "{%0,%1,%2,%3}, {%4,%5,%6,%7}, {%8,%9}, {%0,%1,%2,%3};"              \
        : "+f"((d)[0]), "+f"((d)[1]), "+f"((d)[2]), "+f"((d)[3])             \
        : "r"((a)[0]), "r"((a)[1]), "r"((a)[2]), "r"((a)[3]),                \
          "r"(b0), "r"(b1))

// Kf: base[ns*640 + ((key&7)<<2 | d&3)*20 + (d>>3)*2 + ((d>>2)&1)] = tf32 K[key][d]
__device__ __forceinline__ void scatter_k(float* base, int i, float4 x) {
    int key = i >> 4, dg4 = i & 15;
    int ns = key >> 3, lr = key & 7;
    float vv[4] = {x.x, x.y, x.z, x.w};
    #pragma unroll
    for (int j = 0; j < 4; ++j) {
        int d = dg4 * 4 + j;
        int kk = d >> 3, h = (d >> 2) & 1, cc = d & 3;
        base[ns * 640 + ((lr << 2) | cc) * 20 + kk * 2 + h] = tff(vv[j]);
    }
}
// Vf: base[(d>>3)*640 + ((d&7)<<2 | key&3)*20 + (key>>3)*2 + ((key>>2)&1)] = tf32 V[key][d]
__device__ __forceinline__ void scatter_v(float* base, int i, float4 x) {
    int key = i >> 4, dg4 = i & 15;
    int kk = key >> 3, cc = key & 3, h = (key >> 2) & 1;
    float vv[4] = {x.x, x.y, x.z, x.w};
    #pragma unroll
    for (int j = 0; j < 4; ++j) {
        int d = dg4 * 4 + j;
        int ns = d >> 3, rr = d & 7;
        base[ns * 640 + ((rr << 2) | cc) * 20 + kk * 2 + h] = tff(vv[j]);
    }
}

// ===================== kernel A: QK + exp -> unnormalized att + rowsums (round-12 proven) =====================
extern "C" __global__ void __launch_bounds__(256, 2)
attn_qk(const float* __restrict__ q, const float* __restrict__ k,
        const float* __restrict__ mask, float* __restrict__ att_out) {
    extern __shared__ float sm[];
    const int tid = threadIdx.x, wid = tid >> 5, lane = tid & 31;
    const int r = lane >> 2, c = lane & 3;
    const int bh = blockIdx.y, b = bh >> 4;
    const int qoff = blockIdx.x * 256;

    const float* kb = k + (size_t)bh * S_LEN * DIM;
    const float* mb = mask + b * S_LEN;
    float* attw = att_out + ((size_t)bh * S_LEN + qoff + wid * 32) * S_LEN;

    uint32_t qa[2][8][4];
    {
        const float* qb = q + ((size_t)bh * S_LEN + qoff + wid * 32) * DIM;
        #pragma unroll
        for (int g = 0; g < 2; ++g)
            #pragma unroll
            for (int kk = 0; kk < 8; ++kk) {
                qa[g][kk][0] = __float_as_uint(tff(qb[(16 * g + r)     * DIM + 8 * kk + c]     * SCL));
                qa[g][kk][1] = __float_as_uint(tff(qb[(16 * g + 8 + r) * DIM + 8 * kk + c]     * SCL));
                qa[g][kk][2] = __float_as_uint(tff(qb[(16 * g + r)     * DIM + 8 * kk + c + 4] * SCL));
                qa[g][kk][3] = __float_as_uint(tff(qb[(16 * g + 8 + r) * DIM + 8 * kk + c + 4] * SCL));
            }
    }

    for (int i = tid; i < 1024; i += 256)
        scatter_k(sm + KF(0), i, *(const float4*)(kb + (size_t)(i >> 4) * DIM + (i & 15) * 4));
    if (tid < 64) sm[MSA(0) + tid] = mb[tid] * L2E;
    __syncthreads();

    float rs[2][2] = {};

    for (int t = 0; t < NT; ++t) {
        const int p = t & 1;
        const bool more = (t + 1 < NT);
        float4 kr[4]; float mr = 0.0f;
        if (more) {
            #pragma unroll
            for (int it = 0; it < 4; ++it) {
                int i = tid + it * 256;
                kr[it] = *(const float4*)(kb + ((size_t)(t + 1) * 64 + (i >> 4)) * DIM + (i & 15) * 4);
            }
            if (tid < 64) mr = mb[(t + 1) * 64 + tid];
        }
        #pragma unroll
        for (int half = 0; half < 2; ++half) {
            #pragma unroll
            for (int ns = half * 4; ns < half * 4 + 4; ++ns) {
                float sc0[4] = {}, sc1[4] = {};
                #pragma unroll
                for (int i = 0; i < 4; ++i) {
                    float4 bb = *(const float4*)(sm + KF(p) + ns * 640 + lane * 20 + 4 * i);
                    MMA_TF32(sc0, qa[0][2 * i],     __float_as_uint(bb.x), __float_as_uint(bb.y));
                    MMA_TF32(sc0, qa[0][2 * i + 1], __float_as_uint(bb.z), __float_as_uint(bb.w));
                    MMA_TF32(sc1, qa[1][2 * i],     __float_as_uint(bb.x), __float_as_uint(bb.y));
                    MMA_TF32(sc1, qa[1][2 * i + 1], __float_as_uint(bb.z), __float_as_uint(bb.w));
                }
                float2 mm = ((const float2*)(sm + MSA(p)))[ns * 4 + c];
                int col = t * 64 + 8 * ns + 2 * c;
                {
                    float e0 = exp2_poly(sc0[0] + mm.x), e1 = exp2_poly(sc0[1] + mm.y);
                    float e2 = exp2_poly(sc0[2] + mm.x), e3 = exp2_poly(sc0[3] + mm.y);
                    rs[0][0] += e0 + e1; rs[0][1] += e2 + e3;
                    *(float2*)(attw + (size_t)r       * S_LEN + col) = make_float2(e0, e1);
                    *(float2*)(attw + (size_t)(8 + r) * S_LEN + col) = make_float2(e2, e3);
                }
                {
                    float e0 = exp2_poly(sc1[0] + mm.x), e1 = exp2_poly(sc1[1] + mm.y);
                    float e2 = exp2_poly(sc1[2] + mm.x), e3 = exp2_poly(sc1[3] + mm.y);
                    rs[1][0] += e0 + e1; rs[1][1] += e2 + e3;
                    *(float2*)(attw + (size_t)(16 + r) * S_LEN + col) = make_float2(e0, e1);
                    *(float2*)(attw + (size_t)(24 + r) * S_LEN + col) = make_float2(e2, e3);
                }
            }
            if (half == 0 && more) {
                #pragma unroll
                for (int it = 0; it < 4; ++it) scatter_k(sm + KF(1 - p), tid + it * 256, kr[it]);
                if (tid < 64) sm[MSA(1 - p) + tid] = mr * L2E;
            }
        }
        __syncthreads();
    }

    #pragma unroll
    for (int g = 0; g < 2; ++g)
        #pragma unroll
        for (int b2 = 0; b2 < 2; ++b2) {
            rs[g][b2] += __shfl_xor_sync(0xffffffffu, rs[g][b2], 1);
            rs[g][b2] += __shfl_xor_sync(0xffffffffu, rs[g][b2], 2);
        }
    if (c == 0) {
        size_t base = (size_t)bh * S_LEN + qoff + wid * 32;
        g_rowsum[base + r]      = rs[0][0];
        g_rowsum[base + 8 + r]  = rs[0][1];
        g_rowsum[base + 16 + r] = rs[1][0];
        g_rowsum[base + 24 + r] = rs[1][1];
    }
}

// ===================== kernel B: lean 16-rows/warp normalize + P.V, 3 CTAs/SM =====================
// CTA = 128 q rows; 8 warps x 16 rows. Round-12 per-i4 slice structure halved;
// no prefetch registers -> ~75 regs -> 24 warps/SM for the latency-bound path.
extern "C" __global__ void __launch_bounds__(256, 3)
attn_pv(const float* __restrict__ v, float* __restrict__ att,
        float* __restrict__ ctx_out) {
    extern __shared__ float sm[];
    const int tid = threadIdx.x, wid = tid >> 5, lane = tid & 31;
    const int r = lane >> 2, c = lane & 3;
    const int bh = blockIdx.y;
    const int wrow = blockIdx.x * 128 + wid * 16;

    const float* vb = v + (size_t)bh * S_LEN * DIM;
    float* attw = att + ((size_t)bh * S_LEN + wrow) * S_LEN;
    float* Pst  = sm + PS_OFF + wid * 320;        // [16 rows][20], warp-private

    float inv[2];
    inv[0] = 1.0f / g_rowsum[(size_t)bh * S_LEN + wrow + r];
    inv[1] = 1.0f / g_rowsum[(size_t)bh * S_LEN + wrow + 8 + r];

    for (int i = tid; i < 1024; i += 256)
        scatter_v(sm + VF(0), i, *(const float4*)(vb + (size_t)(i >> 4) * DIM + (i & 15) * 4));
    __syncthreads();

    float cx[8][4] = {};

    for (int t = 0; t < NT; ++t) {
        const int p = t & 1;
        const bool more = (t + 1 < NT);
        #pragma unroll
        for (int i4 = 0; i4 < 4; ++i4) {
            // load att slice (16 rows x 16 keys), normalize, rewrite, stage
            #pragma unroll
            for (int j = 0; j < 2; ++j) {
                float* gp = attw + (size_t)(8 * j + r) * S_LEN + t * 64 + i4 * 16 + 4 * c;
                float4 x = *(const float4*)gp;
                x.x *= inv[j]; x.y *= inv[j]; x.z *= inv[j]; x.w *= inv[j];
                *(float4*)gp = x;
                *(float4*)(Pst + (8 * j + r) * 20 + 4 * c) = x;
            }
            __syncwarp();
            // gather A-frags for k-steps 2*i4, 2*i4+1
            uint32_t pa[2][4];
            #pragma unroll
            for (int kl = 0; kl < 2; ++kl) {
                pa[kl][0] = __float_as_uint(tff(Pst[r * 20 + kl * 8 + c]));
                pa[kl][1] = __float_as_uint(tff(Pst[(8 + r) * 20 + kl * 8 + c]));
                pa[kl][2] = __float_as_uint(tff(Pst[r * 20 + kl * 8 + c + 4]));
                pa[kl][3] = __float_as_uint(tff(Pst[(8 + r) * 20 + kl * 8 + c + 4]));
            }
            #pragma unroll
            for (int nsv = 0; nsv < 8; ++nsv) {
                float4 bb = *(const float4*)(sm + VF(p) + nsv * 640 + lane * 20 + 4 * i4);
                MMA_TF32(cx[nsv], pa[0], __float_as_uint(bb.x), __float_as_uint(bb.y));
                MMA_TF32(cx[nsv], pa[1], __float_as_uint(bb.z), __float_as_uint(bb.w));
            }
            __syncwarp();   // staging reused next i4 (warp-private)
            if (i4 == 1 && more) {
                // refill next V buffer directly from global (no prefetch regs)
                #pragma unroll
                for (int it = 0; it < 4; ++it) {
                    int i = tid + it * 256;
                    scatter_v(sm + VF(1 - p), i,
                              *(const float4*)(vb + ((size_t)(t + 1) * 64 + (i >> 4)) * DIM + (i & 15) * 4));
                }
            }
        }
        __syncthreads();
    }

    float* cb = ctx_out + ((size_t)bh * S_LEN + wrow) * DIM;
    #pragma unroll
    for (int nsv = 0; nsv < 8; ++nsv) {
        *(float2*)(cb + (size_t)r * DIM + 8 * nsv + 2 * c)       = make_float2(cx[nsv][0], cx[nsv][1]);
        *(float2*)(cb + (size_t)(8 + r) * DIM + 8 * nsv + 2 * c) = make_float2(cx[nsv][2], cx[nsv][3]);
    }
}

extern "C" void kernel_launch(void* const* d_in, const int* in_sizes, int n_in,
                              void* d_out, int out_size) {
    const float* q    = (const float*)d_in[0];
    const float* k    = (const float*)d_in[1];
    const float* v    = (const float*)d_in[2];
    const float* mask = (const float*)d_in[3];
    float* ctx = (float*)d_out;                                   // [B,H,S,D]
    float* att = (float*)d_out + (size_t)64 * S_LEN * DIM;        // [B,H,S,S]

    cudaFuncSetAttribute(attn_qk, cudaFuncAttributeMaxDynamicSharedMemorySize,
                         SMA_FLOATS * 4);
    cudaFuncSetAttribute(attn_pv, cudaFuncAttributeMaxDynamicSharedMemorySize,
                         SMB_FLOATS * 4);

    attn_qk<<<dim3(S_LEN / 256, 64), 256, SMA_FLOATS * 4>>>(q, k, mask, att);
    attn_pv<<<dim3(S_LEN / 128, 64), 256, SMB_FLOATS * 4>>>(v, att, ctx);
}

// round 17
// speedup vs baseline: 1.2367x; 1.2367x over previous
#include <cuda_runtime.h>
#include <cstdint>

#define S_LEN 2048
#define DIM   64
#define NT    32                      // 64-key tiles
#define SCL   0.18033688011112042f    // 0.125 * log2(e)
#define L2E   1.4426950408889634f

__device__ float g_rowsum[64 * S_LEN];
__device__ unsigned int g_flag[512];   // zero-init; self-resetting per launch

// ---- unified smem layout (floats). A path uses KF/MSA; B path uses VF/PS. ----
#define KF(b)   ((b) * 5120)
#define MSA(b)  (10240 + (b) * 64)
#define VF(b)   ((b) * 5120)          // V frags, double buffer
#define PS_OFF  10240                 // staging: 8 warps * 32 rows * 20 = 5120
#define SM_FLOATS 15360
#define SM_BYTES  (SM_FLOATS * 4)     // 61440

__device__ __forceinline__ float tff(float x) {      // round-to-nearest tf32
    uint32_t u;
    asm("cvt.rna.tf32.f32 %0, %1;" : "=r"(u) : "f"(x));
    return __uint_as_float(u);
}

__device__ __forceinline__ float exp2_poly(float t) {
    float z = t + 12582912.0f;
    int   j = __float_as_int(z) - 0x4B400000;
    float f = t - (z - 12582912.0f);
    float p =            1.33335581e-3f;
    p = fmaf(p, f, 9.61812910e-3f);
    p = fmaf(p, f, 5.55041087e-2f);
    p = fmaf(p, f, 2.40226507e-1f);
    p = fmaf(p, f, 6.93147180e-1f);
    p = fmaf(p, f, 1.0f);
    return __int_as_float(__float_as_int(p) + (j << 23));
}

#define MMA_TF32(d, a, b0, b1)                                               \
    asm volatile("mma.sync.aligned.m16n8k8.row.col.f32.tf32.tf32.f32 "       \
        "{%0,%1,%2,%3}, {%4,%5,%6,%7}, {%8,%9}, {%0,%1,%2,%3};"              \
        : "+f"((d)[0]), "+f"((d)[1]), "+f"((d)[2]), "+f"((d)[3])             \
        : "r"((a)[0]), "r"((a)[1]), "r"((a)[2]), "r"((a)[3]),                \
          "r"(b0), "r"(b1))

// Kf: base[ns*640 + ((key&7)<<2 | d&3)*20 + (d>>3)*2 + ((d>>2)&1)] = tf32 K[key][d]
__device__ __forceinline__ void scatter_k(float* base, int i, float4 x) {
    int key = i >> 4, dg4 = i & 15;
    int ns = key >> 3, lr = key & 7;
    float vv[4] = {x.x, x.y, x.z, x.w};
    #pragma unroll
    for (int j = 0; j < 4; ++j) {
        int d = dg4 * 4 + j;
        int kk = d >> 3, h = (d >> 2) & 1, cc = d & 3;
        base[ns * 640 + ((lr << 2) | cc) * 20 + kk * 2 + h] = tff(vv[j]);
    }
}
// Vf: base[(d>>3)*640 + ((d&7)<<2 | key&3)*20 + (key>>3)*2 + ((key>>2)&1)] = tf32 V[key][d]
__device__ __forceinline__ void scatter_v(float* base, int i, float4 x) {
    int key = i >> 4, dg4 = i & 15;
    int kk = key >> 3, cc = key & 3, h = (key >> 2) & 1;
    float vv[4] = {x.x, x.y, x.z, x.w};
    #pragma unroll
    for (int j = 0; j < 4; ++j) {
        int d = dg4 * 4 + j;
        int ns = d >> 3, rr = d & 7;
        base[ns * 640 + ((rr << 2) | cc) * 20 + kk * 2 + h] = tff(vv[j]);
    }
}

// ============ path A: QK + exp -> unnormalized att + rowsums (round-14 proven) ============
__device__ void path_qk(float* sm, const float* __restrict__ q,
                        const float* __restrict__ k, const float* __restrict__ mask,
                        float* __restrict__ att_out) {
    const int tid = threadIdx.x, wid = tid >> 5, lane = tid & 31;
    const int r = lane >> 2, c = lane & 3;
    const int bh = blockIdx.y, b = bh >> 4;
    const int qoff = blockIdx.x * 256;

    const float* kb = k + (size_t)bh * S_LEN * DIM;
    const float* mb = mask + b * S_LEN;
    float* attw = att_out + ((size_t)bh * S_LEN + qoff + wid * 32) * S_LEN;

    uint32_t qa[2][8][4];
    {
        const float* qb = q + ((size_t)bh * S_LEN + qoff + wid * 32) * DIM;
        #pragma unroll
        for (int g = 0; g < 2; ++g)
            #pragma unroll
            for (int kk = 0; kk < 8; ++kk) {
                qa[g][kk][0] = __float_as_uint(tff(qb[(16 * g + r)     * DIM + 8 * kk + c]     * SCL));
                qa[g][kk][1] = __float_as_uint(tff(qb[(16 * g + 8 + r) * DIM + 8 * kk + c]     * SCL));
                qa[g][kk][2] = __float_as_uint(tff(qb[(16 * g + r)     * DIM + 8 * kk + c + 4] * SCL));
                qa[g][kk][3] = __float_as_uint(tff(qb[(16 * g + 8 + r) * DIM + 8 * kk + c + 4] * SCL));
            }
    }

    for (int i = tid; i < 1024; i += 256)
        scatter_k(sm + KF(0), i, *(const float4*)(kb + (size_t)(i >> 4) * DIM + (i & 15) * 4));
    if (tid < 64) sm[MSA(0) + tid] = mb[tid] * L2E;
    __syncthreads();

    float rs[2][2] = {};

    for (int t = 0; t < NT; ++t) {
        const int p = t & 1;
        const bool more = (t + 1 < NT);
        float4 kr[4]; float mr = 0.0f;
        if (more) {
            #pragma unroll
            for (int it = 0; it < 4; ++it) {
                int i = tid + it * 256;
                kr[it] = *(const float4*)(kb + ((size_t)(t + 1) * 64 + (i >> 4)) * DIM + (i & 15) * 4);
            }
            if (tid < 64) mr = mb[(t + 1) * 64 + tid];
        }
        #pragma unroll
        for (int half = 0; half < 2; ++half) {
            #pragma unroll
            for (int ns = half * 4; ns < half * 4 + 4; ++ns) {
                float sc0[4] = {}, sc1[4] = {};
                #pragma unroll
                for (int i = 0; i < 4; ++i) {
                    float4 bb = *(const float4*)(sm + KF(p) + ns * 640 + lane * 20 + 4 * i);
                    MMA_TF32(sc0, qa[0][2 * i],     __float_as_uint(bb.x), __float_as_uint(bb.y));
                    MMA_TF32(sc0, qa[0][2 * i + 1], __float_as_uint(bb.z), __float_as_uint(bb.w));
                    MMA_TF32(sc1, qa[1][2 * i],     __float_as_uint(bb.x), __float_as_uint(bb.y));
                    MMA_TF32(sc1, qa[1][2 * i + 1], __float_as_uint(bb.z), __float_as_uint(bb.w));
                }
                float2 mm = ((const float2*)(sm + MSA(p)))[ns * 4 + c];
                int col = t * 64 + 8 * ns + 2 * c;
                {
                    float e0 = exp2_poly(sc0[0] + mm.x), e1 = exp2_poly(sc0[1] + mm.y);
                    float e2 = exp2_poly(sc0[2] + mm.x), e3 = exp2_poly(sc0[3] + mm.y);
                    rs[0][0] += e0 + e1; rs[0][1] += e2 + e3;
                    *(float2*)(attw + (size_t)r       * S_LEN + col) = make_float2(e0, e1);
                    *(float2*)(attw + (size_t)(8 + r) * S_LEN + col) = make_float2(e2, e3);
                }
                {
                    float e0 = exp2_poly(sc1[0] + mm.x), e1 = exp2_poly(sc1[1] + mm.y);
                    float e2 = exp2_poly(sc1[2] + mm.x), e3 = exp2_poly(sc1[3] + mm.y);
                    rs[1][0] += e0 + e1; rs[1][1] += e2 + e3;
                    *(float2*)(attw + (size_t)(16 + r) * S_LEN + col) = make_float2(e0, e1);
                    *(float2*)(attw + (size_t)(24 + r) * S_LEN + col) = make_float2(e2, e3);
                }
            }
            if (half == 0 && more) {
                #pragma unroll
                for (int it = 0; it < 4; ++it) scatter_k(sm + KF(1 - p), tid + it * 256, kr[it]);
                if (tid < 64) sm[MSA(1 - p) + tid] = mr * L2E;
            }
        }
        __syncthreads();
    }

    #pragma unroll
    for (int g = 0; g < 2; ++g)
        #pragma unroll
        for (int b2 = 0; b2 < 2; ++b2) {
            rs[g][b2] += __shfl_xor_sync(0xffffffffu, rs[g][b2], 1);
            rs[g][b2] += __shfl_xor_sync(0xffffffffu, rs[g][b2], 2);
        }
    if (c == 0) {
        size_t base = (size_t)bh * S_LEN + qoff + wid * 32;
        g_rowsum[base + r]      = rs[0][0];
        g_rowsum[base + 8 + r]  = rs[0][1];
        g_rowsum[base + 16 + r] = rs[1][0];
        g_rowsum[base + 24 + r] = rs[1][1];
    }

    __syncthreads();
    __threadfence();
    if (tid == 0)
        atomicExch(&g_flag[blockIdx.y * 8 + blockIdx.x], 1u);
}

// ============ path B: raw-stage + deferred normalize + P.V ============
// Round-12 phase order; FMUL/STG moved off the LDG->MMA chain; cx scaled at end.
__device__ void path_pv(float* sm, const float* __restrict__ v,
                        float* __restrict__ att, float* __restrict__ ctx_out) {
    const int tid = threadIdx.x, wid = tid >> 5, lane = tid & 31;
    const int r = lane >> 2, c = lane & 3;
    const int bh = blockIdx.y;
    const int qoff = blockIdx.x * 256;

    const float* vb = v + (size_t)bh * S_LEN * DIM;

    // ---- independent work first: V tile-0 scatter (hidden under flag latency) ----
    for (int i = tid; i < 1024; i += 256)
        scatter_v(sm + VF(0), i, *(const float4*)(vb + (size_t)(i >> 4) * DIM + (i & 15) * 4));

    // ---- wait for matching A CTA; CAS(1->0) self-resets for graph replay ----
    if (tid == 0) {
        unsigned int* f = &g_flag[blockIdx.y * 8 + blockIdx.x];
        while (atomicCAS(f, 1u, 0u) != 1u) __nanosleep(64);
        __threadfence();
    }
    __syncthreads();

    float* attw = att + ((size_t)bh * S_LEN + qoff + wid * 32) * S_LEN;
    float* Pst  = sm + PS_OFF + wid * 640;        // [32 rows][20], warp-private

    float inv[4];
    #pragma unroll
    for (int j = 0; j < 4; ++j)
        inv[j] = 1.0f / g_rowsum[(size_t)bh * S_LEN + qoff + wid * 32 + 8 * j + r];

    float cx[2][8][4] = {};

    for (int t = 0; t < NT; ++t) {
        const int p = t & 1;
        const bool more = (t + 1 < NT);
        float4 vr[4];
        if (more) {
            #pragma unroll
            for (int it = 0; it < 4; ++it) {
                int i = tid + it * 256;
                vr[it] = *(const float4*)(vb + ((size_t)(t + 1) * 64 + (i >> 4)) * DIM + (i & 15) * 4);
            }
        }
        #pragma unroll
        for (int half = 0; half < 2; ++half) {
            #pragma unroll
            for (int i4 = half * 2; i4 < half * 2 + 2; ++i4) {
                // (a) load att slice raw -> stage immediately (no FMUL on path)
                float4 xr[4];
                #pragma unroll
                for (int j = 0; j < 4; ++j) {
                    xr[j] = *(const float4*)(attw + (size_t)(8 * j + r) * S_LEN + t * 64 + i4 * 16 + 4 * c);
                    *(float4*)(Pst + (8 * j + r) * 20 + 4 * c) = xr[j];
                }
                __syncwarp();
                // (b) gather raw A-frags
                uint32_t pa[2][2][4];
                #pragma unroll
                for (int g = 0; g < 2; ++g)
                    #pragma unroll
                    for (int kl = 0; kl < 2; ++kl) {
                        pa[g][kl][0] = __float_as_uint(tff(Pst[(g * 16 + r)     * 20 + kl * 8 + c]));
                        pa[g][kl][1] = __float_as_uint(tff(Pst[(g * 16 + 8 + r) * 20 + kl * 8 + c]));
                        pa[g][kl][2] = __float_as_uint(tff(Pst[(g * 16 + r)     * 20 + kl * 8 + c + 4]));
                        pa[g][kl][3] = __float_as_uint(tff(Pst[(g * 16 + 8 + r) * 20 + kl * 8 + c + 4]));
                    }
                // (c) normalize + att write-back, off the MMA dependency chain
                #pragma unroll
                for (int j = 0; j < 4; ++j) {
                    xr[j].x *= inv[j]; xr[j].y *= inv[j]; xr[j].z *= inv[j]; xr[j].w *= inv[j];
                    *(float4*)(attw + (size_t)(8 * j + r) * S_LEN + t * 64 + i4 * 16 + 4 * c) = xr[j];
                }
                // (d) MMAs on raw P
                #pragma unroll
                for (int nsv = 0; nsv < 8; ++nsv) {
                    float4 bb = *(const float4*)(sm + VF(p) + nsv * 640 + lane * 20 + 4 * i4);
                    MMA_TF32(cx[0][nsv], pa[0][0], __float_as_uint(bb.x), __float_as_uint(bb.y));
                    MMA_TF32(cx[0][nsv], pa[0][1], __float_as_uint(bb.z), __float_as_uint(bb.w));
                    MMA_TF32(cx[1][nsv], pa[1][0], __float_as_uint(bb.x), __float_as_uint(bb.y));
                    MMA_TF32(cx[1][nsv], pa[1][1], __float_as_uint(bb.z), __float_as_uint(bb.w));
                }
                __syncwarp();   // staging reused next group (warp-private)
            }
            if (half == 0 && more) {
                #pragma unroll
                for (int it = 0; it < 4; ++it) scatter_v(sm + VF(1 - p), tid + it * 256, vr[it]);
            }
        }
        __syncthreads();
    }

    // ---- scale partial ctx by inv, write ----
    float* cb = ctx_out + ((size_t)bh * S_LEN + qoff + wid * 32) * DIM;
    #pragma unroll
    for (int g = 0; g < 2; ++g)
        #pragma unroll
        for (int nsv = 0; nsv < 8; ++nsv) {
            *(float2*)(cb + (size_t)(16 * g + r)     * DIM + 8 * nsv + 2 * c) =
                make_float2(cx[g][nsv][0] * inv[2 * g], cx[g][nsv][1] * inv[2 * g]);
            *(float2*)(cb + (size_t)(16 * g + 8 + r) * DIM + 8 * nsv + 2 * c) =
                make_float2(cx[g][nsv][2] * inv[2 * g + 1], cx[g][nsv][3] * inv[2 * g + 1]);
        }
}

// ============ unified kernel: z=0 -> A CTAs (dispatched first), z=1 -> B CTAs ============
extern "C" __global__ void __launch_bounds__(256, 2)
attn_ab(const float* __restrict__ q, const float* __restrict__ k,
        const float* __restrict__ v, const float* __restrict__ mask,
        float* __restrict__ att, float* __restrict__ ctx) {
    extern __shared__ float sm[];
    if (blockIdx.z == 0)
        path_qk(sm, q, k, mask, att);
    else
        path_pv(sm, v, att, ctx);
}

extern "C" void kernel_launch(void* const* d_in, const int* in_sizes, int n_in,
                              void* d_out, int out_size) {
    const float* q    = (const float*)d_in[0];
    const float* k    = (const float*)d_in[1];
    const float* v    = (const float*)d_in[2];
    const float* mask = (const float*)d_in[3];
    float* ctx = (float*)d_out;                                   // [B,H,S,D]
    float* att = (float*)d_out + (size_t)64 * S_LEN * DIM;        // [B,H,S,S]

    cudaFuncSetAttribute(attn_ab, cudaFuncAttributeMaxDynamicSharedMemorySize,
                         SM_BYTES);
    attn_ab<<<dim3(8, 64, 2), 256, SM_BYTES>>>(q, k, v, mask, att, ctx);
}